// round 10
// baseline (speedup 1.0000x reference)
#include <cuda_runtime.h>

#define NROWS 2048
#define DFEAT 128
#define BLOCK 128
#define WPB   (BLOCK / 32)
#define GRID  (NROWS / WPB)
#define MAXNZ 320

__global__ __launch_bounds__(BLOCK) void distance_warprow_kernel(
    const float* __restrict__ feats,
    const float* __restrict__ adj,
    float* __restrict__ out)
{
    const int tid  = threadIdx.x;
    const int lane = tid & 31;
    const int warp = tid >> 5;
    const int sub  = lane & 7;    // sublane within 8-lane group
    const int grp  = lane >> 3;   // group 0..3: one column per group

    __shared__ int   nzidx[WPB][MAXNZ];   // 5 KB
    __shared__ float evals[WPB][MAXNZ];   // 5 KB

    const int i = blockIdx.x * WPB + warp;         // this warp's row

    const float4* arow4 = reinterpret_cast<const float4*>(adj + (size_t)i * NROWS);
    const float4* fi4p  = reinterpret_cast<const float4*>(feats + (size_t)i * DFEAT);
    float*        orow  = out + (size_t)i * NROWS;
    float4*       orow4 = reinterpret_cast<float4*>(orow);

    int*   nz = nzidx[warp];
    float* ev = evals[warp];
    const unsigned lt = (1u << lane) - 1u;

    // ---- zero-fill this row's output early (fire-and-forget gmem stores;
    //      ordered before the final scatter by the __syncwarp fences below) ----
    const float4 z4 = make_float4(0.f, 0.f, 0.f, 0.f);
    #pragma unroll
    for (int t = 0; t < 16; t++) orow4[t * 32 + lane] = z4;

    // fi slices: this lane's 4 float4 pieces of feats[i]
    float4 fi[4];
    #pragma unroll
    for (int t = 0; t < 4; t++) fi[t] = fi4p[sub + 8 * t];

    // ---- Stage A: scan adj row, warp-local ballot compaction (int stores) ----
    int base = 0;
    #pragma unroll
    for (int h = 0; h < 2; h++) {
        float4 av[8];
        #pragma unroll
        for (int t = 0; t < 8; t++) av[t] = arow4[h * 256 + t * 32 + lane];
        #pragma unroll
        for (int t = 0; t < 8; t++) {
            const int col = (h * 256 + t * 32 + lane) * 4;
            unsigned b;
            b = __ballot_sync(0xffffffffu, av[t].x != 0.f);
            if (av[t].x != 0.f) nz[base + __popc(b & lt)] = col;
            base += __popc(b);
            b = __ballot_sync(0xffffffffu, av[t].y != 0.f);
            if (av[t].y != 0.f) nz[base + __popc(b & lt)] = col + 1;
            base += __popc(b);
            b = __ballot_sync(0xffffffffu, av[t].z != 0.f);
            if (av[t].z != 0.f) nz[base + __popc(b & lt)] = col + 2;
            base += __popc(b);
            b = __ballot_sync(0xffffffffu, av[t].w != 0.f);
            if (av[t].w != 0.f) nz[base + __popc(b & lt)] = col + 3;
            base += __popc(b);
        }
    }
    const int m = base;           // warp-uniform
    __syncwarp();                 // nz visible to all lanes; zero-fill ordered

    // ---- Stage B: 8-lane group per column, 2x4 columns per pass (R7-proven),
    //      leaders store distances densely by compaction index ----
    for (int k = 0; k < m; k += 8) {
        const int  iA = k + grp;
        const int  iB = k + 4 + grp;
        const bool aA = iA < m;
        const bool aB = iB < m;
        const int  jA = aA ? nz[iA] : 0;
        const int  jB = aB ? nz[iB] : 0;
        const float4* fA = reinterpret_cast<const float4*>(feats + (size_t)jA * DFEAT);
        const float4* fB = reinterpret_cast<const float4*>(feats + (size_t)jB * DFEAT);

        float sA = 0.f, sB = 0.f;
        #pragma unroll
        for (int t = 0; t < 4; t++) {
            const float4 v = fA[sub + 8 * t];
            sA += (fabsf(fi[t].x - v.x) + fabsf(fi[t].y - v.y))
                + (fabsf(fi[t].z - v.z) + fabsf(fi[t].w - v.w));
        }
        #pragma unroll
        for (int t = 0; t < 4; t++) {
            const float4 v = fB[sub + 8 * t];
            sB += (fabsf(fi[t].x - v.x) + fabsf(fi[t].y - v.y))
                + (fabsf(fi[t].z - v.z) + fabsf(fi[t].w - v.w));
        }
        #pragma unroll
        for (int o = 4; o >= 1; o >>= 1) {
            sA += __shfl_xor_sync(0xffffffffu, sA, o);
            sB += __shfl_xor_sync(0xffffffffu, sB, o);
        }
        if (sub == 0) {
            if (aA) ev[iA] = sA;
            if (aB) ev[iB] = sB;
        }
    }
    __syncwarp();                 // leaders' ev stores visible to all lanes

    // ---- Stage C: uniform batched exp + full-warp rowsum reduction ----
    float local = 0.f;
    for (int t = lane; t < m; t += 32) {
        const float e = __expf(-0.01f * ev[t]);
        ev[t] = e;                // same lane re-reads below; no fence needed
        local += e;
    }
    #pragma unroll
    for (int o = 16; o >= 1; o >>= 1)
        local += __shfl_xor_sync(0xffffffffu, local, o);
    const float inv = 1.0f / fmaxf(local, 1e-12f);

    // ---- Stage D: scatter normalized values over the zero-filled row ----
    for (int t = lane; t < m; t += 32)
        orow[nz[t]] = ev[t] * inv;
}

extern "C" void kernel_launch(void* const* d_in, const int* in_sizes, int n_in,
                              void* d_out, int out_size)
{
    const float* feats = (const float*)d_in[0];
    const float* adj   = (const float*)d_in[1];
    float* out         = (float*)d_out;
    distance_warprow_kernel<<<GRID, BLOCK>>>(feats, adj, out);
}

// round 11
// speedup vs baseline: 1.1308x; 1.1308x over previous
#include <cuda_runtime.h>

#define NROWS  2048
#define DFEAT  128
#define BLOCK  128
#define WPB    4          // warps per block; each warp owns 512 columns
#define MAXNZW 128        // >=20 sigma above mean nnz (25.6) per 512-col chunk

__global__ __launch_bounds__(BLOCK, 12) void distance_rowsplit_kernel(
    const float* __restrict__ feats,
    const float* __restrict__ adj,
    float* __restrict__ out)
{
    const int tid  = threadIdx.x;
    const int lane = tid & 31;
    const int warp = tid >> 5;
    const int sub  = lane & 7;    // sublane within 8-lane group
    const int grp  = lane >> 3;   // group 0..3: one column per group

    __shared__ int   nzidx[WPB][MAXNZW];   // 2 KB
    __shared__ float evals[WPB][MAXNZW];   // 2 KB
    __shared__ float wpart[WPB];

    const int i = blockIdx.x;              // this block's row

    const float4* arow4 = reinterpret_cast<const float4*>(adj + (size_t)i * NROWS);
    const float4* fi4p  = reinterpret_cast<const float4*>(feats + (size_t)i * DFEAT);
    float*        orow  = out + (size_t)i * NROWS;
    float4*       orow4 = reinterpret_cast<float4*>(orow);

    int*   nz = nzidx[warp];
    float* ev = evals[warp];
    const unsigned lt = (1u << lane) - 1u;

    // ---- this warp's 512-column chunk: 4 float4 per lane, issued first ----
    float4 av[4];
    #pragma unroll
    for (int t = 0; t < 4; t++) av[t] = arow4[warp * 128 + t * 32 + lane];

    // fi slices (L1/L2 hot)
    float4 fi[4];
    #pragma unroll
    for (int t = 0; t < 4; t++) fi[t] = fi4p[sub + 8 * t];

    // ---- zero-fill this warp's quarter of the output row (fire-and-forget;
    //      ordered before the scatter by the __syncthreads below) ----
    const float4 z4 = make_float4(0.f, 0.f, 0.f, 0.f);
    #pragma unroll
    for (int t = 0; t < 4; t++) orow4[warp * 128 + t * 32 + lane] = z4;

    // ---- Stage A: warp-local ballot compaction of this chunk ----
    int base = 0;
    #pragma unroll
    for (int t = 0; t < 4; t++) {
        const int col = (warp * 128 + t * 32 + lane) * 4;
        unsigned b;
        b = __ballot_sync(0xffffffffu, av[t].x != 0.f);
        if (av[t].x != 0.f) nz[base + __popc(b & lt)] = col;
        base += __popc(b);
        b = __ballot_sync(0xffffffffu, av[t].y != 0.f);
        if (av[t].y != 0.f) nz[base + __popc(b & lt)] = col + 1;
        base += __popc(b);
        b = __ballot_sync(0xffffffffu, av[t].z != 0.f);
        if (av[t].z != 0.f) nz[base + __popc(b & lt)] = col + 2;
        base += __popc(b);
        b = __ballot_sync(0xffffffffu, av[t].w != 0.f);
        if (av[t].w != 0.f) nz[base + __popc(b & lt)] = col + 3;
        base += __popc(b);
    }
    const int m = base;          // warp-uniform
    __syncwarp();                // nz visible to all lanes

    // ---- Stage B: 8-lane group per column, 2x4 columns per pass ----
    for (int k = 0; k < m; k += 8) {
        const int  iA = k + grp;
        const int  iB = k + 4 + grp;
        const bool aA = iA < m;
        const bool aB = iB < m;
        const int  jA = aA ? nz[iA] : 0;
        const int  jB = aB ? nz[iB] : 0;
        const float4* fA = reinterpret_cast<const float4*>(feats + (size_t)jA * DFEAT);
        const float4* fB = reinterpret_cast<const float4*>(feats + (size_t)jB * DFEAT);

        float sA = 0.f, sB = 0.f;
        #pragma unroll
        for (int t = 0; t < 4; t++) {
            const float4 v = fA[sub + 8 * t];
            sA += (fabsf(fi[t].x - v.x) + fabsf(fi[t].y - v.y))
                + (fabsf(fi[t].z - v.z) + fabsf(fi[t].w - v.w));
        }
        #pragma unroll
        for (int t = 0; t < 4; t++) {
            const float4 v = fB[sub + 8 * t];
            sB += (fabsf(fi[t].x - v.x) + fabsf(fi[t].y - v.y))
                + (fabsf(fi[t].z - v.z) + fabsf(fi[t].w - v.w));
        }
        #pragma unroll
        for (int o = 4; o >= 1; o >>= 1) {
            sA += __shfl_xor_sync(0xffffffffu, sA, o);
            sB += __shfl_xor_sync(0xffffffffu, sB, o);
        }
        if (sub == 0) {
            if (aA) ev[iA] = sA;
            if (aB) ev[iB] = sB;
        }
    }
    __syncwarp();                // leaders' ev stores visible warp-wide

    // ---- Stage C: batched exp + warp partial rowsum ----
    float local = 0.f;
    for (int t = lane; t < m; t += 32) {
        const float e = __expf(-0.01f * ev[t]);
        ev[t] = e;               // same lane re-reads below
        local += e;
    }
    #pragma unroll
    for (int o = 16; o >= 1; o >>= 1)
        local += __shfl_xor_sync(0xffffffffu, local, o);
    if (lane == 0) wpart[warp] = local;

    // ---- single block barrier: combine 4 partial sums ----
    __syncthreads();
    const float s   = wpart[0] + wpart[1] + wpart[2] + wpart[3];
    const float inv = 1.0f / fmaxf(s, 1e-12f);

    // ---- Stage D: scatter this warp's normalized values over its quarter ----
    for (int t = lane; t < m; t += 32)
        orow[nz[t]] = ev[t] * inv;
}

extern "C" void kernel_launch(void* const* d_in, const int* in_sizes, int n_in,
                              void* d_out, int out_size)
{
    const float* feats = (const float*)d_in[0];
    const float* adj   = (const float*)d_in[1];
    float* out         = (float*)d_out;
    distance_rowsplit_kernel<<<NROWS, BLOCK>>>(feats, adj, out);
}

// round 12
// speedup vs baseline: 1.2432x; 1.0993x over previous
#include <cuda_runtime.h>

#define NROWS 2048
#define DFEAT 128
#define BLOCK 256
#define NWARP (BLOCK / 32)
#define ROWB  (DFEAT * 4)   // 512 bytes per feats row

__global__ __launch_bounds__(BLOCK) void distance_sparse_kernel(
    const float* __restrict__ feats,
    const float* __restrict__ adj,
    float* __restrict__ out)
{
    const int i    = blockIdx.x;
    const int tid  = threadIdx.x;
    const int lane = tid & 31;
    const int warp = tid >> 5;
    const int sub  = lane & 7;    // sublane within 8-lane group
    const int grp  = lane >> 3;   // group 0..3: one column per group

    __shared__ float row[NROWS];     // 8 KB dense e-row
    __shared__ int   nzoff[NROWS];   // 8 KB byte offsets (col*512)
    __shared__ int   cnt;
    __shared__ float rowsum;

    if (tid == 0) { cnt = 0; rowsum = 0.0f; }
    #pragma unroll
    for (int t = tid; t < NROWS; t += BLOCK) row[t] = 0.0f;

    // fi slices: sub + 8t, t=0..3
    const float4* fi4p = reinterpret_cast<const float4*>(feats + (size_t)i * DFEAT);
    float4 fi[4];
    #pragma unroll
    for (int t = 0; t < 4; t++) fi[t] = fi4p[sub + 8 * t];
    __syncthreads();

    // ---- Phase 1: ballot-compact nonzero columns as BYTE OFFSETS ----
    const float4* arow4 = reinterpret_cast<const float4*>(adj + (size_t)i * NROWS);
    const unsigned lt = (1u << lane) - 1u;
    #pragma unroll
    for (int t = tid; t < NROWS / 4; t += BLOCK) {
        const float4 a = arow4[t];
        const unsigned b0 = __ballot_sync(0xffffffffu, a.x != 0.0f);
        const unsigned b1 = __ballot_sync(0xffffffffu, a.y != 0.0f);
        const unsigned b2 = __ballot_sync(0xffffffffu, a.z != 0.0f);
        const unsigned b3 = __ballot_sync(0xffffffffu, a.w != 0.0f);
        const int c0 = __popc(b0), c1 = __popc(b1), c2 = __popc(b2), c3 = __popc(b3);
        int base = 0;
        if (lane == 0) base = atomicAdd(&cnt, c0 + c1 + c2 + c3);
        base = __shfl_sync(0xffffffffu, base, 0);
        const int off = t * 4 * ROWB;
        if (a.x != 0.0f) nzoff[base + __popc(b0 & lt)]                = off;
        if (a.y != 0.0f) nzoff[base + c0 + __popc(b1 & lt)]           = off + ROWB;
        if (a.z != 0.0f) nzoff[base + c0 + c1 + __popc(b2 & lt)]      = off + 2 * ROWB;
        if (a.w != 0.0f) nzoff[base + c0 + c1 + c2 + __popc(b3 & lt)] = off + 3 * ROWB;
    }
    __syncthreads();
    const int m = cnt;

    // ---- Phase 2: 8-lane group per column, 4 cols/pass, 2x unrolled;
    //      all 8 gather loads issued before any FADD ----
    const char* fbase = reinterpret_cast<const char*>(feats);
    const int   lane_off = sub * 16;   // this lane's byte offset within a row
    float wsum = 0.0f;
    for (int k4 = warp; k4 * 4 < m; k4 += 2 * NWARP) {
        const int  idxA = k4 * 4 + grp;
        const int  idxB = (k4 + NWARP) * 4 + grp;
        const bool actA = idxA < m;
        const bool actB = idxB < m;
        const int  oA = actA ? nzoff[idxA] : 0;
        const int  oB = actB ? nzoff[idxB] : 0;
        const char* pA = fbase + oA + lane_off;
        const char* pB = fbase + oB + lane_off;

        float4 fa[4], fb[4];
        #pragma unroll
        for (int t = 0; t < 4; t++) fa[t] = *reinterpret_cast<const float4*>(pA + t * 128);
        #pragma unroll
        for (int t = 0; t < 4; t++) fb[t] = *reinterpret_cast<const float4*>(pB + t * 128);

        float sA = 0.0f, sB = 0.0f;
        #pragma unroll
        for (int t = 0; t < 4; t++)
            sA += (fabsf(fi[t].x - fa[t].x) + fabsf(fi[t].y - fa[t].y))
                + (fabsf(fi[t].z - fa[t].z) + fabsf(fi[t].w - fa[t].w));
        #pragma unroll
        for (int t = 0; t < 4; t++)
            sB += (fabsf(fi[t].x - fb[t].x) + fabsf(fi[t].y - fb[t].y))
                + (fabsf(fi[t].z - fb[t].z) + fabsf(fi[t].w - fb[t].w));

        #pragma unroll
        for (int o = 4; o >= 1; o >>= 1) {
            sA += __shfl_xor_sync(0xffffffffu, sA, o);
            sB += __shfl_xor_sync(0xffffffffu, sB, o);
        }
        if (sub == 0) {
            if (actA) { const float e = __expf(-0.01f * sA); row[oA >> 9] = e; wsum += e; }
            if (actB) { const float e = __expf(-0.01f * sB); row[oB >> 9] = e; wsum += e; }
        }
    }
    // combine group leaders (lanes 0,8,16,24)
    wsum += __shfl_xor_sync(0xffffffffu, wsum, 8);
    wsum += __shfl_xor_sync(0xffffffffu, wsum, 16);
    if (lane == 0 && wsum != 0.0f) atomicAdd(&rowsum, wsum);
    __syncthreads();

    // ---- Phase 3: normalize + stream full row out ----
    const float inv = 1.0f / fmaxf(rowsum, 1e-12f);
    float4* orow4 = reinterpret_cast<float4*>(out + (size_t)i * NROWS);
    const float4* row4 = reinterpret_cast<const float4*>(row);
    #pragma unroll
    for (int t = tid; t < NROWS / 4; t += BLOCK) {
        float4 v = row4[t];
        v.x *= inv; v.y *= inv; v.z *= inv; v.w *= inv;
        orow4[t] = v;
    }
}

extern "C" void kernel_launch(void* const* d_in, const int* in_sizes, int n_in,
                              void* d_out, int out_size)
{
    const float* feats = (const float*)d_in[0];
    const float* adj   = (const float*)d_in[1];
    float* out         = (float*)d_out;
    distance_sparse_kernel<<<NROWS, BLOCK>>>(feats, adj, out);
}